// round 11
// baseline (speedup 1.0000x reference)
#include <cuda_runtime.h>
#include <cuda_fp16.h>
#include <stdint.h>
#include <math.h>

#define NN 384
#define CIN 128
#define DH 32
#define NH 4
#define M_TOT (NN*NN)   // 147456

#define SKS 36          // attn smem row stride (u32) for K/V interleaved hi/lo
#define PRS 136         // proj/out smem row stride in fp16 (272B, conflict-free ldsm)

// ---------------- scratch ----------------
__device__ __half g_xnh[(size_t)M_TOT*CIN];     // layernormed x, fp16
__device__ float g_triB[(size_t)NH*M_TOT];      // [h][q][j]
__device__ float g_G[(size_t)M_TOT*CIN];        // [i][h][j][d]
__device__ __half g_OGh[(size_t)M_TOT*CIN];     // gated attention out, fp16 [m][h*32+d]
__device__ __half g_Bw[(size_t)512*CIN];        // qkvg weights [n=512][k=128] fp16
__device__ __half g_Bwo[(size_t)CIN*CIN];       // wo [c][k] fp16
// fp16 hi/lo planes, all [i][h][j][d]
__device__ __half g_Qh[(size_t)M_TOT*CIN];
__device__ __half g_Ql[(size_t)M_TOT*CIN];
__device__ __half g_Kh[(size_t)M_TOT*CIN];
__device__ __half g_Kl[(size_t)M_TOT*CIN];
__device__ __half g_Vh[(size_t)M_TOT*CIN];
__device__ __half g_Vl[(size_t)M_TOT*CIN];

// fp16 hi/lo split of a float pair
__device__ __forceinline__ void split_h(float a, float b, uint32_t& hi, uint32_t& lo) {
    __half2 H = __floats2half2_rn(a, b);
    float2 hf = __half22float2(H);
    __half2 L = __floats2half2_rn(a - hf.x, b - hf.y);
    hi = *(uint32_t*)&H; lo = *(uint32_t*)&L;
}

__device__ __forceinline__ void mma_f16(float* c, const uint32_t* a, uint32_t b0, uint32_t b1) {
    asm volatile("mma.sync.aligned.m16n8k16.row.col.f32.f16.f16.f32 "
        "{%0,%1,%2,%3}, {%4,%5,%6,%7}, {%8,%9}, {%0,%1,%2,%3};"
        : "+f"(c[0]), "+f"(c[1]), "+f"(c[2]), "+f"(c[3])
        : "r"(a[0]), "r"(a[1]), "r"(a[2]), "r"(a[3]), "r"(b0), "r"(b1));
}

__device__ __forceinline__ void ldsm4(uint32_t* r, uint32_t addr) {
    asm volatile("ldmatrix.sync.aligned.m8n8.x4.shared.b16 {%0,%1,%2,%3}, [%4];"
        : "=r"(r[0]), "=r"(r[1]), "=r"(r[2]), "=r"(r[3]) : "r"(addr));
}
__device__ __forceinline__ void ldsm4t(uint32_t* r, uint32_t addr) {
    asm volatile("ldmatrix.sync.aligned.m8n8.x4.trans.shared.b16 {%0,%1,%2,%3}, [%4];"
        : "=r"(r[0]), "=r"(r[1]), "=r"(r[2]), "=r"(r[3]) : "r"(addr));
}

// ---------------- K0: pack weights (fp16, [n][k] natural layout) ----------------
__global__ void pack_kernel(const float* __restrict__ wq, const float* __restrict__ wk,
                            const float* __restrict__ wv, const float* __restrict__ wg,
                            const float* __restrict__ wo) {
    int idx = blockIdx.x * 256 + threadIdx.x;
    if (idx < 512 * CIN) {
        int n = idx >> 7, k = idx & 127;
        int h = n >> 7, t = n & 127, sub = t >> 5, d = t & 31;
        const float* w = (sub == 0) ? wq : (sub == 1) ? wk : (sub == 2) ? wv : wg;
        float val = w[(h * DH + d) * CIN + k];
        if (sub == 0) val *= 0.17677669529663687f;   // 1/sqrt(32)
        g_Bw[idx] = __float2half_rn(val);
    }
    if (idx < CIN * CIN) {
        g_Bwo[idx] = __float2half_rn(wo[idx]);       // wo already [c][k]
    }
}

// ---------------- K1: LayerNorm + triangle bias ----------------
__global__ void __launch_bounds__(256) ln_kernel(const float* __restrict__ x,
                                                 const float* __restrict__ gamma,
                                                 const float* __restrict__ beta,
                                                 const float* __restrict__ wbias) {
    int wid = threadIdx.x >> 5, lane = threadIdx.x & 31;
    int p = blockIdx.x * 8 + wid;
    const float4 v = ((const float4*)(x + (size_t)p * CIN))[lane];
    float s  = v.x + v.y + v.z + v.w;
    float sq = v.x*v.x + v.y*v.y + v.z*v.z + v.w*v.w;
    #pragma unroll
    for (int o = 16; o; o >>= 1) {
        s  += __shfl_xor_sync(~0u, s,  o);
        sq += __shfl_xor_sync(~0u, sq, o);
    }
    float mu   = s * (1.f / 128.f);
    float var  = sq * (1.f / 128.f) - mu * mu;
    float rstd = rsqrtf(var + 1e-5f);
    float4 g4 = ((const float4*)gamma)[lane];
    float4 b4 = ((const float4*)beta)[lane];
    float4 xn;
    xn.x = (v.x - mu) * rstd * g4.x + b4.x;
    xn.y = (v.y - mu) * rstd * g4.y + b4.y;
    xn.z = (v.z - mu) * rstd * g4.z + b4.z;
    xn.w = (v.w - mu) * rstd * g4.w + b4.w;

    #pragma unroll
    for (int h = 0; h < NH; h++) {
        float4 w4 = ((const float4*)(wbias + h * CIN))[lane];
        float d = xn.x*w4.x + xn.y*w4.y + xn.z*w4.z + xn.w*w4.w;
        #pragma unroll
        for (int o = 16; o; o >>= 1) d += __shfl_xor_sync(~0u, d, o);
        if (lane == 0) g_triB[(size_t)h * M_TOT + p] = d;
    }

    __half2 h0 = __floats2half2_rn(xn.x, xn.y);
    __half2 h1 = __floats2half2_rn(xn.z, xn.w);
    uint2 u; u.x = *(uint32_t*)&h0; u.y = *(uint32_t*)&h1;
    ((uint2*)(g_xnh + (size_t)p * CIN))[lane] = u;
}

// ---------------- K2: projection GEMM (fp16 mma) + staged coalesced epilogue ----------------
__global__ void __launch_bounds__(256, 1) proj_mma_kernel(const float* __restrict__ bg) {
    extern __shared__ char smc[];
    __half* As = (__half*)smc;           // [128][PRS]
    __half* Bs = As + 128 * PRS;         // [128][PRS]
    int tid = threadIdx.x;
    int h   = blockIdx.x;
    int m0  = blockIdx.y * 128;

    const uint4* Ag = (const uint4*)(g_xnh + (size_t)m0 * CIN);
    const uint4* Bg = (const uint4*)(g_Bw + (size_t)h * 128 * CIN);
    #pragma unroll
    for (int r = 0; r < 8; r++) {
        int f = tid + r * 256;           // 2048 uint4
        int row = f >> 4, c8 = f & 15;
        *(uint4*)(As + row * PRS + c8 * 8) = Ag[f];
        *(uint4*)(Bs + row * PRS + c8 * 8) = Bg[f];
    }
    __syncthreads();

    int warp = tid >> 5, lane = tid & 31;
    int wm = (warp >> 1) * 32;
    int wn = (warp & 1) * 64;
    int lr = lane & 7, lsel = (lane >> 3) & 1, ltile = lane >> 4;
    uint32_t abase = (uint32_t)__cvta_generic_to_shared(As);
    uint32_t bbase = (uint32_t)__cvta_generic_to_shared(Bs);

    float c[2][8][4];
    #pragma unroll
    for (int a = 0; a < 2; a++)
        #pragma unroll
        for (int b = 0; b < 8; b++)
            #pragma unroll
            for (int e = 0; e < 4; e++) c[a][b][e] = 0.f;

    #pragma unroll
    for (int k0 = 0; k0 < 128; k0 += 16) {
        uint32_t a[2][4];
        #pragma unroll
        for (int mt = 0; mt < 2; mt++) {
            // A groups: (m0-7,k0),(m8-15,k0),(m0-7,k8),(m8-15,k8)
            int arow = wm + mt * 16 + lsel * 8 + lr;
            int akoff = k0 + ltile * 8;
            ldsm4(a[mt], abase + (arow * PRS + akoff) * 2);
        }
        #pragma unroll
        for (int ntp = 0; ntp < 4; ntp++) {
            // B groups: (n0-7,k0),(n0-7,k8),(n8-15,k0),(n8-15,k8)
            int brow = wn + ntp * 16 + ltile * 8 + lr;
            int bkoff = k0 + lsel * 8;
            uint32_t b[4];
            ldsm4(b, bbase + (brow * PRS + bkoff) * 2);
            #pragma unroll
            for (int mt = 0; mt < 2; mt++) {
                mma_f16(c[mt][2*ntp],   a[mt], b[0], b[1]);
                mma_f16(c[mt][2*ntp+1], a[mt], b[2], b[3]);
            }
        }
    }
    __syncthreads();

    int g = lane >> 2, tg = lane & 3;
    float* Cs = (float*)smc;     // [128][132], fits in 2*128*PRS*2 bytes
    #pragma unroll
    for (int nt = 0; nt < 8; nt++) {
        int col = wn + nt * 8 + 2 * tg;
        #pragma unroll
        for (int mt = 0; mt < 2; mt++) {
            int r0 = wm + mt * 16 + g;
            *(float2*)(Cs + r0 * 132 + col)       = make_float2(c[mt][nt][0], c[mt][nt][1]);
            *(float2*)(Cs + (r0 + 8) * 132 + col) = make_float2(c[mt][nt][2], c[mt][nt][3]);
        }
    }
    __syncthreads();

    int m_l = tid & 127, role = tid >> 7;
    int m = m0 + m_l;
    int i = m / NN, j = m - i * NN;
    size_t hb = (size_t)(i * NH + h) * NN * DH + (size_t)j * DH;
    const float* row = Cs + m_l * 132;

    if (role == 0) {
        #pragma unroll
        for (int s = 0; s < 2; s++) {
            const float* src = row + s * 32;
            __half* dh = (s == 0 ? g_Qh : g_Kh) + hb;
            __half* dl = (s == 0 ? g_Ql : g_Kl) + hb;
            #pragma unroll
            for (int b = 0; b < 4; b++) {
                float4 x0 = *(const float4*)(src + b * 8);
                float4 x1 = *(const float4*)(src + b * 8 + 4);
                uint32_t h0, l0, h1, l1, h2, l2, h3, l3;
                split_h(x0.x, x0.y, h0, l0);
                split_h(x0.z, x0.w, h1, l1);
                split_h(x1.x, x1.y, h2, l2);
                split_h(x1.z, x1.w, h3, l3);
                *(uint4*)(dh + b * 8) = make_uint4(h0, h1, h2, h3);
                *(uint4*)(dl + b * 8) = make_uint4(l0, l1, l2, l3);
            }
        }
    } else {
        {
            const float* src = row + 64;
            #pragma unroll
            for (int b = 0; b < 4; b++) {
                float4 x0 = *(const float4*)(src + b * 8);
                float4 x1 = *(const float4*)(src + b * 8 + 4);
                uint32_t h0, l0, h1, l1, h2, l2, h3, l3;
                split_h(x0.x, x0.y, h0, l0);
                split_h(x0.z, x0.w, h1, l1);
                split_h(x1.x, x1.y, h2, l2);
                split_h(x1.z, x1.w, h3, l3);
                *(uint4*)(g_Vh + hb + b * 8) = make_uint4(h0, h1, h2, h3);
                *(uint4*)(g_Vl + hb + b * 8) = make_uint4(l0, l1, l2, l3);
            }
        }
        {
            const float* src = row + 96;
            #pragma unroll
            for (int b = 0; b < 8; b++) {
                float4 x = *(const float4*)(src + b * 4);
                float4 o;
                o.x = 1.f / (1.f + __expf(-(x.x + __ldg(bg + h * DH + b * 4 + 0))));
                o.y = 1.f / (1.f + __expf(-(x.y + __ldg(bg + h * DH + b * 4 + 1))));
                o.z = 1.f / (1.f + __expf(-(x.z + __ldg(bg + h * DH + b * 4 + 2))));
                o.w = 1.f / (1.f + __expf(-(x.w + __ldg(bg + h * DH + b * 4 + 3))));
                *(float4*)(g_G + hb + b * 4) = o;
            }
        }
    }
}

// ---------------- K3: attention, fp16 mma (QK 3-term, PV 2-term with single-P) ----------------
__global__ void __launch_bounds__(256) attn_f16_kernel(const float* __restrict__ mask) {
    extern __shared__ uint32_t smu[];
    uint32_t* Ks = smu;
    uint32_t* Vs = smu + 384 * SKS;
    float*    ms = (float*)(smu + 2 * 384 * SKS);

    int i = blockIdx.x, h = blockIdx.y;
    int tid = threadIdx.x, warp = tid >> 5, lane = tid & 31;
    int g = lane >> 2, tg = lane & 3;
    size_t base = (size_t)(i * NH + h) * NN * DH;
    uint32_t sbase = (uint32_t)__cvta_generic_to_shared(smu);
    uint32_t vbase = sbase + 384 * SKS * 4;

    {
        const uint4* Kh4 = (const uint4*)(g_Kh + base);
        const uint4* Kl4 = (const uint4*)(g_Kl + base);
        const uint4* Vh4 = (const uint4*)(g_Vh + base);
        const uint4* Vl4 = (const uint4*)(g_Vl + base);
        #pragma unroll
        for (int r = 0; r < 6; r++) {
            int f = tid + r * 256;
            int j = f >> 2, b = f & 3;
            *(uint4*)(Ks + j * SKS + 8 * b)     = Kh4[f];
            *(uint4*)(Ks + j * SKS + 8 * b + 4) = Kl4[f];
            *(uint4*)(Vs + j * SKS + 8 * b)     = Vh4[f];
            *(uint4*)(Vs + j * SKS + 8 * b + 4) = Vl4[f];
        }
        for (int t = tid; t < NN; t += 256)
            ms[t] = (__ldg(mask + (size_t)i * NN + t) - 1.f) * 1e9f;
    }
    __syncthreads();

    const float* biasH = g_triB + (size_t)h * M_TOT;
    const uint32_t* Qhp = (const uint32_t*)(g_Qh + base);
    const uint32_t* Qlp = (const uint32_t*)(g_Ql + base);

    int lr = lane & 7;
    int lsel = (lane >> 3) & 1;
    int ltile = lane >> 4;

    for (int qt = 0; qt < 3; qt++) {
        int q0 = qt * 128 + warp * 16;

        uint32_t aQh[2][4], aQl[2][4];
        #pragma unroll
        for (int kc = 0; kc < 2; kc++) {
            int u0 = (q0 + g) * 16 + kc * 8 + tg;
            int u1 = (q0 + g + 8) * 16 + kc * 8 + tg;
            aQh[kc][0] = __ldg(Qhp + u0);     aQh[kc][1] = __ldg(Qhp + u1);
            aQh[kc][2] = __ldg(Qhp + u0 + 4); aQh[kc][3] = __ldg(Qhp + u1 + 4);
            aQl[kc][0] = __ldg(Qlp + u0);     aQl[kc][1] = __ldg(Qlp + u1);
            aQl[kc][2] = __ldg(Qlp + u0 + 4); aQl[kc][3] = __ldg(Qlp + u1 + 4);
        }

        float m0 = -1e30f, m1 = -1e30f, l0 = 0.f, l1 = 0.f;
        float O[4][4];
        #pragma unroll
        for (int a = 0; a < 4; a++)
            #pragma unroll
            for (int e = 0; e < 4; e++) O[a][e] = 0.f;

        for (int ch = 0; ch < 6; ch++) {
            int j0 = ch * 64;
            float c[8][4];
            #pragma unroll
            for (int nt = 0; nt < 8; nt++)
                #pragma unroll
                for (int e = 0; e < 4; e++) c[nt][e] = 0.f;

            #pragma unroll
            for (int kc = 0; kc < 2; kc++) {
                #pragma unroll
                for (int p = 0; p < 4; p++) {
                    int rowj = j0 + 16 * p + ltile * 8 + lr;
                    uint32_t addr = sbase + (rowj * SKS + 8 * (2 * kc + lsel)) * 4;
                    uint32_t bh[4], bl[4];
                    ldsm4(bh, addr);
                    ldsm4(bl, addr + 16);
                    mma_f16(c[2*p],   aQh[kc], bh[0], bh[1]);
                    mma_f16(c[2*p],   aQh[kc], bl[0], bl[1]);
                    mma_f16(c[2*p],   aQl[kc], bh[0], bh[1]);
                    mma_f16(c[2*p+1], aQh[kc], bh[2], bh[3]);
                    mma_f16(c[2*p+1], aQh[kc], bl[2], bl[3]);
                    mma_f16(c[2*p+1], aQl[kc], bh[2], bh[3]);
                }
            }

            float mx0 = -1e30f, mx1 = -1e30f;
            #pragma unroll
            for (int nt = 0; nt < 8; nt++) {
                int jj = j0 + nt * 8 + 2 * tg;
                float2 b0 = __ldg((const float2*)(biasH + (size_t)(q0 + g) * NN + jj));
                float2 b1 = __ldg((const float2*)(biasH + (size_t)(q0 + g + 8) * NN + jj));
                float2 mm = *(float2*)(ms + jj);
                c[nt][0] += b0.x + mm.x; c[nt][1] += b0.y + mm.y;
                c[nt][2] += b1.x + mm.x; c[nt][3] += b1.y + mm.y;
                mx0 = fmaxf(mx0, fmaxf(c[nt][0], c[nt][1]));
                mx1 = fmaxf(mx1, fmaxf(c[nt][2], c[nt][3]));
            }
            mx0 = fmaxf(mx0, __shfl_xor_sync(~0u, mx0, 1));
            mx0 = fmaxf(mx0, __shfl_xor_sync(~0u, mx0, 2));
            mx1 = fmaxf(mx1, __shfl_xor_sync(~0u, mx1, 1));
            mx1 = fmaxf(mx1, __shfl_xor_sync(~0u, mx1, 2));

            float mn0 = fmaxf(m0, mx0), mn1 = fmaxf(m1, mx1);
            float cr0 = __expf(m0 - mn0), cr1 = __expf(m1 - mn1);
            float s0 = 0.f, s1 = 0.f;
            #pragma unroll
            for (int nt = 0; nt < 8; nt++) {
                c[nt][0] = __expf(c[nt][0] - mn0); c[nt][1] = __expf(c[nt][1] - mn0);
                c[nt][2] = __expf(c[nt][2] - mn1); c[nt][3] = __expf(c[nt][3] - mn1);
                s0 += c[nt][0] + c[nt][1];
                s1 += c[nt][2] + c[nt][3];
            }
            s0 += __shfl_xor_sync(~0u, s0, 1); s0 += __shfl_xor_sync(~0u, s0, 2);
            s1 += __shfl_xor_sync(~0u, s1, 1); s1 += __shfl_xor_sync(~0u, s1, 2);
            l0 = l0 * cr0 + s0; l1 = l1 * cr1 + s1;
            m0 = mn0; m1 = mn1;
            #pragma unroll
            for (int nt2 = 0; nt2 < 4; nt2++) {
                O[nt2][0] *= cr0; O[nt2][1] *= cr0;
                O[nt2][2] *= cr1; O[nt2][3] *= cr1;
            }

            #pragma unroll
            for (int kc = 0; kc < 4; kc++) {
                uint32_t ph[4];
                __half2 p0 = __floats2half2_rn(c[2*kc][0],   c[2*kc][1]);
                __half2 p1 = __floats2half2_rn(c[2*kc][2],   c[2*kc][3]);
                __half2 p2 = __floats2half2_rn(c[2*kc+1][0], c[2*kc+1][1]);
                __half2 p3 = __floats2half2_rn(c[2*kc+1][2], c[2*kc+1][3]);
                ph[0] = *(uint32_t*)&p0; ph[1] = *(uint32_t*)&p1;
                ph[2] = *(uint32_t*)&p2; ph[3] = *(uint32_t*)&p3;
                int rowj = j0 + 16 * kc + lsel * 8 + lr;
                #pragma unroll
                for (int pd = 0; pd < 2; pd++) {
                    uint32_t addr = vbase + (rowj * SKS + 8 * (2 * pd + ltile)) * 4;
                    uint32_t bh[4], bl[4];
                    ldsm4t(bh, addr);
                    ldsm4t(bl, addr + 16);
                    mma_f16(O[2*pd],   ph, bh[0], bh[1]);
                    mma_f16(O[2*pd],   ph, bl[0], bl[1]);
                    mma_f16(O[2*pd+1], ph, bh[2], bh[3]);
                    mma_f16(O[2*pd+1], ph, bl[2], bl[3]);
                }
            }
        }

        // finalize: normalize, gate, store fp16
        float iv0 = 1.f / l0, iv1 = 1.f / l1;
        #pragma unroll
        for (int nt2 = 0; nt2 < 4; nt2++) {
            int d = nt2 * 8 + 2 * tg;
            int qa = q0 + g, qb = q0 + g + 8;
            float2 ga = *(const float2*)(g_G + base + (size_t)qa * DH + d);
            float2 gb = *(const float2*)(g_G + base + (size_t)qb * DH + d);
            __half2 oa = __floats2half2_rn(O[nt2][0] * iv0 * ga.x, O[nt2][1] * iv0 * ga.y);
            __half2 ob = __floats2half2_rn(O[nt2][2] * iv1 * gb.x, O[nt2][3] * iv1 * gb.y);
            *(uint32_t*)(g_OGh + (size_t)(i * NN + qa) * CIN + h * DH + d) = *(uint32_t*)&oa;
            *(uint32_t*)(g_OGh + (size_t)(i * NN + qb) * CIN + h * DH + d) = *(uint32_t*)&ob;
        }
    }
}

// ---------------- K4: output GEMM via fp16 mma ----------------
__global__ void __launch_bounds__(256, 1) out_mma_kernel(const float* __restrict__ bo,
                                                         float* __restrict__ out) {
    extern __shared__ char smc[];
    __half* As = (__half*)smc;           // [128][PRS]
    __half* Bs = As + 128 * PRS;
    int tid = threadIdx.x;
    int m0  = blockIdx.x * 128;

    const uint4* Ag = (const uint4*)(g_OGh + (size_t)m0 * CIN);
    const uint4* Bg = (const uint4*)g_Bwo;
    #pragma unroll
    for (int r = 0; r < 8; r++) {
        int f = tid + r * 256;
        int row = f >> 4, c8 = f & 15;
        *(uint4*)(As + row * PRS + c8 * 8) = Ag[f];
        *(uint4*)(Bs + row * PRS + c8 * 8) = Bg[f];
    }
    __syncthreads();

    int warp = tid >> 5, lane = tid & 31;
    int wm = (warp >> 1) * 32;
    int wn = (warp & 1) * 64;
    int lr = lane & 7, lsel = (lane >> 3) & 1, ltile = lane >> 4;
    int g = lane >> 2, tg = lane & 3;
    uint32_t abase = (uint32_t)__cvta_generic_to_shared(As);
    uint32_t bbase = (uint32_t)__cvta_generic_to_shared(Bs);

    float c[2][8][4];
    #pragma unroll
    for (int a = 0; a < 2; a++)
        #pragma unroll
        for (int b = 0; b < 8; b++)
            #pragma unroll
            for (int e = 0; e < 4; e++) c[a][b][e] = 0.f;

    #pragma unroll
    for (int k0 = 0; k0 < 128; k0 += 16) {
        uint32_t a[2][4];
        #pragma unroll
        for (int mt = 0; mt < 2; mt++) {
            int arow = wm + mt * 16 + lsel * 8 + lr;
            int akoff = k0 + ltile * 8;
            ldsm4(a[mt], abase + (arow * PRS + akoff) * 2);
        }
        #pragma unroll
        for (int ntp = 0; ntp < 4; ntp++) {
            int brow = wn + ntp * 16 + ltile * 8 + lr;
            int bkoff = k0 + lsel * 8;
            uint32_t b[4];
            ldsm4(b, bbase + (brow * PRS + bkoff) * 2);
            #pragma unroll
            for (int mt = 0; mt < 2; mt++) {
                mma_f16(c[mt][2*ntp],   a[mt], b[0], b[1]);
                mma_f16(c[mt][2*ntp+1], a[mt], b[2], b[3]);
            }
        }
    }

    #pragma unroll
    for (int nt = 0; nt < 8; nt++) {
        int n = wn + nt * 8 + 2 * tg;
        float bo0 = __ldg(bo + n), bo1 = __ldg(bo + n + 1);
        #pragma unroll
        for (int mt = 0; mt < 2; mt++) {
            #pragma unroll
            for (int rr = 0; rr < 2; rr++) {
                int m = m0 + wm + mt * 16 + g + rr * 8;
                float* dst = out + (size_t)m * CIN + n;
                *(float2*)dst = make_float2(c[mt][nt][rr*2+0] + bo0,
                                            c[mt][nt][rr*2+1] + bo1);
            }
        }
    }
}

// ---------------- launch ----------------
extern "C" void kernel_launch(void* const* d_in, const int* in_sizes, int n_in,
                              void* d_out, int out_size) {
    const float* x     = (const float*)d_in[0];
    const float* mask  = (const float*)d_in[1];
    const float* gamma = (const float*)d_in[2];
    const float* beta  = (const float*)d_in[3];
    const float* wbias = (const float*)d_in[4];
    const float* wq    = (const float*)d_in[5];
    const float* wk    = (const float*)d_in[6];
    const float* wv    = (const float*)d_in[7];
    const float* wg    = (const float*)d_in[8];
    const float* bg    = (const float*)d_in[9];
    const float* wo    = (const float*)d_in[10];
    const float* bo    = (const float*)d_in[11];
    float* out = (float*)d_out;

    const int smem_gemm = 2 * 128 * PRS * 2;           // 69632 (also covers 128*132*4 C-stage)
    const int smem_attn = (2 * 384 * SKS + 384) * 4;   // 112128
    cudaFuncSetAttribute(proj_mma_kernel, cudaFuncAttributeMaxDynamicSharedMemorySize, smem_gemm);
    cudaFuncSetAttribute(out_mma_kernel,  cudaFuncAttributeMaxDynamicSharedMemorySize, smem_gemm);
    cudaFuncSetAttribute(attn_f16_kernel, cudaFuncAttributeMaxDynamicSharedMemorySize, smem_attn);

    pack_kernel<<<256, 256>>>(wq, wk, wv, wg, wo);
    ln_kernel<<<M_TOT / 8, 256>>>(x, gamma, beta, wbias);
    proj_mma_kernel<<<dim3(NH, M_TOT / 128), 256, smem_gemm>>>(bg);
    attn_f16_kernel<<<dim3(NN, NH), 256, smem_attn>>>(mask);
    out_mma_kernel<<<M_TOT / 128, 256, smem_gemm>>>(bo, out);
}

// round 14
// speedup vs baseline: 1.4686x; 1.4686x over previous
#include <cuda_runtime.h>
#include <cuda_fp16.h>
#include <stdint.h>
#include <math.h>

#define NN 384
#define CIN 128
#define DH 32
#define NH 4
#define M_TOT (NN*NN)   // 147456

#define SKS 36          // attn smem row stride (u32) for K/V interleaved hi/lo
#define PRS 136         // proj/out smem row stride in fp16 (272B, conflict-free ldsm)

// ---------------- scratch ----------------
__device__ __half g_xnh[(size_t)M_TOT*CIN];     // layernormed x, fp16
__device__ float g_triB[(size_t)NH*M_TOT];      // [h][q][j]
__device__ float g_G[(size_t)M_TOT*CIN];        // [i][h][j][d]
__device__ __half g_OGh[(size_t)M_TOT*CIN];     // gated attention out, fp16 [m][h*32+d]
__device__ __half g_Bw[(size_t)512*CIN];        // qkvg weights [n=512][k=128] fp16
__device__ __half g_Bwo[(size_t)CIN*CIN];       // wo [c][k] fp16
// fp16 hi/lo planes, all [i][h][j][d]
__device__ __half g_Qh[(size_t)M_TOT*CIN];
__device__ __half g_Ql[(size_t)M_TOT*CIN];
__device__ __half g_Kh[(size_t)M_TOT*CIN];
__device__ __half g_Kl[(size_t)M_TOT*CIN];
__device__ __half g_Vh[(size_t)M_TOT*CIN];
__device__ __half g_Vl[(size_t)M_TOT*CIN];

// fp16 hi/lo split of a float pair
__device__ __forceinline__ void split_h(float a, float b, uint32_t& hi, uint32_t& lo) {
    __half2 H = __floats2half2_rn(a, b);
    float2 hf = __half22float2(H);
    __half2 L = __floats2half2_rn(a - hf.x, b - hf.y);
    hi = *(uint32_t*)&H; lo = *(uint32_t*)&L;
}

__device__ __forceinline__ void mma_f16(float* c, const uint32_t* a, uint32_t b0, uint32_t b1) {
    asm volatile("mma.sync.aligned.m16n8k16.row.col.f32.f16.f16.f32 "
        "{%0,%1,%2,%3}, {%4,%5,%6,%7}, {%8,%9}, {%0,%1,%2,%3};"
        : "+f"(c[0]), "+f"(c[1]), "+f"(c[2]), "+f"(c[3])
        : "r"(a[0]), "r"(a[1]), "r"(a[2]), "r"(a[3]), "r"(b0), "r"(b1));
}

__device__ __forceinline__ void ldsm4(uint32_t* r, uint32_t addr) {
    asm volatile("ldmatrix.sync.aligned.m8n8.x4.shared.b16 {%0,%1,%2,%3}, [%4];"
        : "=r"(r[0]), "=r"(r[1]), "=r"(r[2]), "=r"(r[3]) : "r"(addr));
}
__device__ __forceinline__ void ldsm4t(uint32_t* r, uint32_t addr) {
    asm volatile("ldmatrix.sync.aligned.m8n8.x4.trans.shared.b16 {%0,%1,%2,%3}, [%4];"
        : "=r"(r[0]), "=r"(r[1]), "=r"(r[2]), "=r"(r[3]) : "r"(addr));
}

// ---------------- K0: pack weights (fp16, [n][k] natural layout) ----------------
__global__ void pack_kernel(const float* __restrict__ wq, const float* __restrict__ wk,
                            const float* __restrict__ wv, const float* __restrict__ wg,
                            const float* __restrict__ wo) {
    int idx = blockIdx.x * 256 + threadIdx.x;
    if (idx < 512 * CIN) {
        int n = idx >> 7, k = idx & 127;
        int h = n >> 7, t = n & 127, sub = t >> 5, d = t & 31;
        const float* w = (sub == 0) ? wq : (sub == 1) ? wk : (sub == 2) ? wv : wg;
        float val = w[(h * DH + d) * CIN + k];
        if (sub == 0) val *= 0.17677669529663687f;   // 1/sqrt(32)
        g_Bw[idx] = __float2half_rn(val);
    }
    if (idx < CIN * CIN) {
        g_Bwo[idx] = __float2half_rn(wo[idx]);       // wo already [c][k]
    }
}

// ---------------- K1: LayerNorm + triangle bias ----------------
__global__ void __launch_bounds__(256) ln_kernel(const float* __restrict__ x,
                                                 const float* __restrict__ gamma,
                                                 const float* __restrict__ beta,
                                                 const float* __restrict__ wbias) {
    int wid = threadIdx.x >> 5, lane = threadIdx.x & 31;
    int p = blockIdx.x * 8 + wid;
    const float4 v = ((const float4*)(x + (size_t)p * CIN))[lane];
    float s  = v.x + v.y + v.z + v.w;
    float sq = v.x*v.x + v.y*v.y + v.z*v.z + v.w*v.w;
    #pragma unroll
    for (int o = 16; o; o >>= 1) {
        s  += __shfl_xor_sync(~0u, s,  o);
        sq += __shfl_xor_sync(~0u, sq, o);
    }
    float mu   = s * (1.f / 128.f);
    float var  = sq * (1.f / 128.f) - mu * mu;
    float rstd = rsqrtf(var + 1e-5f);
    float4 g4 = ((const float4*)gamma)[lane];
    float4 b4 = ((const float4*)beta)[lane];
    float4 xn;
    xn.x = (v.x - mu) * rstd * g4.x + b4.x;
    xn.y = (v.y - mu) * rstd * g4.y + b4.y;
    xn.z = (v.z - mu) * rstd * g4.z + b4.z;
    xn.w = (v.w - mu) * rstd * g4.w + b4.w;

    #pragma unroll
    for (int h = 0; h < NH; h++) {
        float4 w4 = ((const float4*)(wbias + h * CIN))[lane];
        float d = xn.x*w4.x + xn.y*w4.y + xn.z*w4.z + xn.w*w4.w;
        #pragma unroll
        for (int o = 16; o; o >>= 1) d += __shfl_xor_sync(~0u, d, o);
        if (lane == 0) g_triB[(size_t)h * M_TOT + p] = d;
    }

    __half2 h0 = __floats2half2_rn(xn.x, xn.y);
    __half2 h1 = __floats2half2_rn(xn.z, xn.w);
    uint2 u; u.x = *(uint32_t*)&h0; u.y = *(uint32_t*)&h1;
    ((uint2*)(g_xnh + (size_t)p * CIN))[lane] = u;
}

// ---------------- K2: projection GEMM (fp16 mma) + staged coalesced epilogue ----------------
__global__ void __launch_bounds__(256, 1) proj_mma_kernel(const float* __restrict__ bg) {
    extern __shared__ char smc[];
    __half* As = (__half*)smc;           // [128][PRS]
    __half* Bs = As + 128 * PRS;         // [128][PRS]
    int tid = threadIdx.x;
    int h   = blockIdx.x;
    int m0  = blockIdx.y * 128;

    const uint4* Ag = (const uint4*)(g_xnh + (size_t)m0 * CIN);
    const uint4* Bg = (const uint4*)(g_Bw + (size_t)h * 128 * CIN);
    #pragma unroll
    for (int r = 0; r < 8; r++) {
        int f = tid + r * 256;           // 2048 uint4
        int row = f >> 4, c8 = f & 15;
        *(uint4*)(As + row * PRS + c8 * 8) = Ag[f];
        *(uint4*)(Bs + row * PRS + c8 * 8) = Bg[f];
    }
    __syncthreads();

    int warp = tid >> 5, lane = tid & 31;
    int wm = (warp >> 1) * 32;
    int wn = (warp & 1) * 64;
    int lr = lane & 7, lsel = (lane >> 3) & 1, ltile = lane >> 4;
    uint32_t abase = (uint32_t)__cvta_generic_to_shared(As);
    uint32_t bbase = (uint32_t)__cvta_generic_to_shared(Bs);

    float c[2][8][4];
    #pragma unroll
    for (int a = 0; a < 2; a++)
        #pragma unroll
        for (int b = 0; b < 8; b++)
            #pragma unroll
            for (int e = 0; e < 4; e++) c[a][b][e] = 0.f;

    #pragma unroll
    for (int k0 = 0; k0 < 128; k0 += 16) {
        uint32_t a[2][4];
        #pragma unroll
        for (int mt = 0; mt < 2; mt++) {
            int arow = wm + mt * 16 + lsel * 8 + lr;
            int akoff = k0 + ltile * 8;
            ldsm4(a[mt], abase + (arow * PRS + akoff) * 2);
        }
        #pragma unroll
        for (int ntp = 0; ntp < 4; ntp++) {
            int brow = wn + ntp * 16 + ltile * 8 + lr;
            int bkoff = k0 + lsel * 8;
            uint32_t b[4];
            ldsm4(b, bbase + (brow * PRS + bkoff) * 2);
            #pragma unroll
            for (int mt = 0; mt < 2; mt++) {
                mma_f16(c[mt][2*ntp],   a[mt], b[0], b[1]);
                mma_f16(c[mt][2*ntp+1], a[mt], b[2], b[3]);
            }
        }
    }
    __syncthreads();

    int g = lane >> 2, tg = lane & 3;
    float* Cs = (float*)smc;     // [128][132]
    #pragma unroll
    for (int nt = 0; nt < 8; nt++) {
        int col = wn + nt * 8 + 2 * tg;
        #pragma unroll
        for (int mt = 0; mt < 2; mt++) {
            int r0 = wm + mt * 16 + g;
            *(float2*)(Cs + r0 * 132 + col)       = make_float2(c[mt][nt][0], c[mt][nt][1]);
            *(float2*)(Cs + (r0 + 8) * 132 + col) = make_float2(c[mt][nt][2], c[mt][nt][3]);
        }
    }
    __syncthreads();

    int m_l = tid & 127, role = tid >> 7;
    int m = m0 + m_l;
    int i = m / NN, j = m - i * NN;
    size_t hb = (size_t)(i * NH + h) * NN * DH + (size_t)j * DH;
    const float* row = Cs + m_l * 132;

    if (role == 0) {
        #pragma unroll
        for (int s = 0; s < 2; s++) {
            const float* src = row + s * 32;
            __half* dh = (s == 0 ? g_Qh : g_Kh) + hb;
            __half* dl = (s == 0 ? g_Ql : g_Kl) + hb;
            #pragma unroll
            for (int b = 0; b < 4; b++) {
                float4 x0 = *(const float4*)(src + b * 8);
                float4 x1 = *(const float4*)(src + b * 8 + 4);
                uint32_t h0, l0, h1, l1, h2, l2, h3, l3;
                split_h(x0.x, x0.y, h0, l0);
                split_h(x0.z, x0.w, h1, l1);
                split_h(x1.x, x1.y, h2, l2);
                split_h(x1.z, x1.w, h3, l3);
                *(uint4*)(dh + b * 8) = make_uint4(h0, h1, h2, h3);
                *(uint4*)(dl + b * 8) = make_uint4(l0, l1, l2, l3);
            }
        }
    } else {
        {
            const float* src = row + 64;
            #pragma unroll
            for (int b = 0; b < 4; b++) {
                float4 x0 = *(const float4*)(src + b * 8);
                float4 x1 = *(const float4*)(src + b * 8 + 4);
                uint32_t h0, l0, h1, l1, h2, l2, h3, l3;
                split_h(x0.x, x0.y, h0, l0);
                split_h(x0.z, x0.w, h1, l1);
                split_h(x1.x, x1.y, h2, l2);
                split_h(x1.z, x1.w, h3, l3);
                *(uint4*)(g_Vh + hb + b * 8) = make_uint4(h0, h1, h2, h3);
                *(uint4*)(g_Vl + hb + b * 8) = make_uint4(l0, l1, l2, l3);
            }
        }
        {
            const float* src = row + 96;
            #pragma unroll
            for (int b = 0; b < 8; b++) {
                float4 x = *(const float4*)(src + b * 4);
                float4 o;
                o.x = 1.f / (1.f + __expf(-(x.x + __ldg(bg + h * DH + b * 4 + 0))));
                o.y = 1.f / (1.f + __expf(-(x.y + __ldg(bg + h * DH + b * 4 + 1))));
                o.z = 1.f / (1.f + __expf(-(x.z + __ldg(bg + h * DH + b * 4 + 2))));
                o.w = 1.f / (1.f + __expf(-(x.w + __ldg(bg + h * DH + b * 4 + 3))));
                *(float4*)(g_G + hb + b * 4) = o;
            }
        }
    }
}

// ---------------- K3: attention, fp16 mma (QK 3-term, PV 2-term), bias L1-prefetch ----------------
__global__ void __launch_bounds__(256, 2) attn_f16_kernel(const float* __restrict__ mask) {
    extern __shared__ uint32_t smu[];
    uint32_t* Ks = smu;
    uint32_t* Vs = smu + 384 * SKS;
    float*    ms = (float*)(smu + 2 * 384 * SKS);

    int i = blockIdx.x, h = blockIdx.y;
    int tid = threadIdx.x, warp = tid >> 5, lane = tid & 31;
    int g = lane >> 2, tg = lane & 3;
    size_t base = (size_t)(i * NH + h) * NN * DH;
    uint32_t sbase = (uint32_t)__cvta_generic_to_shared(smu);
    uint32_t vbase = sbase + 384 * SKS * 4;

    {
        const uint4* Kh4 = (const uint4*)(g_Kh + base);
        const uint4* Kl4 = (const uint4*)(g_Kl + base);
        const uint4* Vh4 = (const uint4*)(g_Vh + base);
        const uint4* Vl4 = (const uint4*)(g_Vl + base);
        #pragma unroll
        for (int r = 0; r < 6; r++) {
            int f = tid + r * 256;
            int j = f >> 2, b = f & 3;
            *(uint4*)(Ks + j * SKS + 8 * b)     = Kh4[f];
            *(uint4*)(Ks + j * SKS + 8 * b + 4) = Kl4[f];
            *(uint4*)(Vs + j * SKS + 8 * b)     = Vh4[f];
            *(uint4*)(Vs + j * SKS + 8 * b + 4) = Vl4[f];
        }
        for (int t = tid; t < NN; t += 256)
            ms[t] = (__ldg(mask + (size_t)i * NN + t) - 1.f) * 1e9f;
    }
    __syncthreads();

    const float* biasH = g_triB + (size_t)h * M_TOT;
    const uint32_t* Qhp = (const uint32_t*)(g_Qh + base);
    const uint32_t* Qlp = (const uint32_t*)(g_Ql + base);

    int lr = lane & 7;
    int lsel = (lane >> 3) & 1;
    int ltile = lane >> 4;
    // bias prefetch lane map: rows q0+g / q0+g+8, the two 128B lines of each 64-col span
    int pf_rowoff = (tg & 2) ? 8 : 0;
    int pf_coloff = (tg & 1) * 32;

    for (int qt = 0; qt < 3; qt++) {
        int q0 = qt * 128 + warp * 16;

        // prefetch chunk-0 bias lines into L1
        {
            const float* pf = biasH + (size_t)(q0 + g + pf_rowoff) * NN + pf_coloff;
            asm volatile("prefetch.global.L1 [%0];" :: "l"(pf));
        }

        uint32_t aQh[2][4], aQl[2][4];
        #pragma unroll
        for (int kc = 0; kc < 2; kc++) {
            int u0 = (q0 + g) * 16 + kc * 8 + tg;
            int u1 = (q0 + g + 8) * 16 + kc * 8 + tg;
            aQh[kc][0] = __ldg(Qhp + u0);     aQh[kc][1] = __ldg(Qhp + u1);
            aQh[kc][2] = __ldg(Qhp + u0 + 4); aQh[kc][3] = __ldg(Qhp + u1 + 4);
            aQl[kc][0] = __ldg(Qlp + u0);     aQl[kc][1] = __ldg(Qlp + u1);
            aQl[kc][2] = __ldg(Qlp + u0 + 4); aQl[kc][3] = __ldg(Qlp + u1 + 4);
        }

        float m0 = -1e30f, m1 = -1e30f, l0 = 0.f, l1 = 0.f;
        float O[4][4];
        #pragma unroll
        for (int a = 0; a < 4; a++)
            #pragma unroll
            for (int e = 0; e < 4; e++) O[a][e] = 0.f;

        for (int ch = 0; ch < 6; ch++) {
            int j0 = ch * 64;

            // prefetch NEXT chunk's bias lines into L1 (overlaps with QK mma below)
            if (ch < 5) {
                const float* pf = biasH + (size_t)(q0 + g + pf_rowoff) * NN + (j0 + 64) + pf_coloff;
                asm volatile("prefetch.global.L1 [%0];" :: "l"(pf));
            }

            float c[8][4];
            #pragma unroll
            for (int nt = 0; nt < 8; nt++)
                #pragma unroll
                for (int e = 0; e < 4; e++) c[nt][e] = 0.f;

            #pragma unroll
            for (int kc = 0; kc < 2; kc++) {
                #pragma unroll
                for (int p = 0; p < 4; p++) {
                    int rowj = j0 + 16 * p + ltile * 8 + lr;
                    uint32_t addr = sbase + (rowj * SKS + 8 * (2 * kc + lsel)) * 4;
                    uint32_t bh[4], bl[4];
                    ldsm4(bh, addr);
                    ldsm4(bl, addr + 16);
                    mma_f16(c[2*p],   aQh[kc], bh[0], bh[1]);
                    mma_f16(c[2*p],   aQh[kc], bl[0], bl[1]);
                    mma_f16(c[2*p],   aQl[kc], bh[0], bh[1]);
                    mma_f16(c[2*p+1], aQh[kc], bh[2], bh[3]);
                    mma_f16(c[2*p+1], aQh[kc], bl[2], bl[3]);
                    mma_f16(c[2*p+1], aQl[kc], bh[2], bh[3]);
                }
            }

            float mx0 = -1e30f, mx1 = -1e30f;
            #pragma unroll
            for (int nt = 0; nt < 8; nt++) {
                int jj = j0 + nt * 8 + 2 * tg;
                float2 b0 = __ldg((const float2*)(biasH + (size_t)(q0 + g) * NN + jj));
                float2 b1 = __ldg((const float2*)(biasH + (size_t)(q0 + g + 8) * NN + jj));
                float2 mm = *(float2*)(ms + jj);
                c[nt][0] += b0.x + mm.x; c[nt][1] += b0.y + mm.y;
                c[nt][2] += b1.x + mm.x; c[nt][3] += b1.y + mm.y;
                mx0 = fmaxf(mx0, fmaxf(c[nt][0], c[nt][1]));
                mx1 = fmaxf(mx1, fmaxf(c[nt][2], c[nt][3]));
            }
            mx0 = fmaxf(mx0, __shfl_xor_sync(~0u, mx0, 1));
            mx0 = fmaxf(mx0, __shfl_xor_sync(~0u, mx0, 2));
            mx1 = fmaxf(mx1, __shfl_xor_sync(~0u, mx1, 1));
            mx1 = fmaxf(mx1, __shfl_xor_sync(~0u, mx1, 2));

            float mn0 = fmaxf(m0, mx0), mn1 = fmaxf(m1, mx1);
            float cr0 = __expf(m0 - mn0), cr1 = __expf(m1 - mn1);
            float s0 = 0.f, s1 = 0.f;
            #pragma unroll
            for (int nt = 0; nt < 8; nt++) {
                c[nt][0] = __expf(c[nt][0] - mn0); c[nt][1] = __expf(c[nt][1] - mn0);
                c[nt][2] = __expf(c[nt][2] - mn1); c[nt][3] = __expf(c[nt][3] - mn1);
                s0 += c[nt][0] + c[nt][1];
                s1 += c[nt][2] + c[nt][3];
            }
            s0 += __shfl_xor_sync(~0u, s0, 1); s0 += __shfl_xor_sync(~0u, s0, 2);
            s1 += __shfl_xor_sync(~0u, s1, 1); s1 += __shfl_xor_sync(~0u, s1, 2);
            l0 = l0 * cr0 + s0; l1 = l1 * cr1 + s1;
            m0 = mn0; m1 = mn1;
            #pragma unroll
            for (int nt2 = 0; nt2 < 4; nt2++) {
                O[nt2][0] *= cr0; O[nt2][1] *= cr0;
                O[nt2][2] *= cr1; O[nt2][3] *= cr1;
            }

            #pragma unroll
            for (int kc = 0; kc < 4; kc++) {
                uint32_t ph[4];
                __half2 p0 = __floats2half2_rn(c[2*kc][0],   c[2*kc][1]);
                __half2 p1 = __floats2half2_rn(c[2*kc][2],   c[2*kc][3]);
                __half2 p2 = __floats2half2_rn(c[2*kc+1][0], c[2*kc+1][1]);
                __half2 p3 = __floats2half2_rn(c[2*kc+1][2], c[2*kc+1][3]);
                ph[0] = *(uint32_t*)&p0; ph[1] = *(uint32_t*)&p1;
                ph[2] = *(uint32_t*)&p2; ph[3] = *(uint32_t*)&p3;
                int rowj = j0 + 16 * kc + lsel * 8 + lr;
                #pragma unroll
                for (int pd = 0; pd < 2; pd++) {
                    uint32_t addr = vbase + (rowj * SKS + 8 * (2 * pd + ltile)) * 4;
                    uint32_t bh[4], bl[4];
                    ldsm4t(bh, addr);
                    ldsm4t(bl, addr + 16);
                    mma_f16(O[2*pd],   ph, bh[0], bh[1]);
                    mma_f16(O[2*pd],   ph, bl[0], bl[1]);
                    mma_f16(O[2*pd+1], ph, bh[2], bh[3]);
                    mma_f16(O[2*pd+1], ph, bl[2], bl[3]);
                }
            }
        }

        // finalize: normalize, gate, store fp16
        float iv0 = 1.f / l0, iv1 = 1.f / l1;
        #pragma unroll
        for (int nt2 = 0; nt2 < 4; nt2++) {
            int d = nt2 * 8 + 2 * tg;
            int qa = q0 + g, qb = q0 + g + 8;
            float2 ga = *(const float2*)(g_G + base + (size_t)qa * DH + d);
            float2 gb = *(const float2*)(g_G + base + (size_t)qb * DH + d);
            __half2 oa = __floats2half2_rn(O[nt2][0] * iv0 * ga.x, O[nt2][1] * iv0 * ga.y);
            __half2 ob = __floats2half2_rn(O[nt2][2] * iv1 * gb.x, O[nt2][3] * iv1 * gb.y);
            *(uint32_t*)(g_OGh + (size_t)(i * NN + qa) * CIN + h * DH + d) = *(uint32_t*)&oa;
            *(uint32_t*)(g_OGh + (size_t)(i * NN + qb) * CIN + h * DH + d) = *(uint32_t*)&ob;
        }
    }
}

// ---------------- K4: output GEMM via fp16 mma ----------------
__global__ void __launch_bounds__(256, 1) out_mma_kernel(const float* __restrict__ bo,
                                                         float* __restrict__ out) {
    extern __shared__ char smc[];
    __half* As = (__half*)smc;           // [128][PRS]
    __half* Bs = As + 128 * PRS;
    int tid = threadIdx.x;
    int m0  = blockIdx.x * 128;

    const uint4* Ag = (const uint4*)(g_OGh + (size_t)m0 * CIN);
    const uint4* Bg = (const uint4*)g_Bwo;
    #pragma unroll
    for (int r = 0; r < 8; r++) {
        int f = tid + r * 256;
        int row = f >> 4, c8 = f & 15;
        *(uint4*)(As + row * PRS + c8 * 8) = Ag[f];
        *(uint4*)(Bs + row * PRS + c8 * 8) = Bg[f];
    }
    __syncthreads();

    int warp = tid >> 5, lane = tid & 31;
    int wm = (warp >> 1) * 32;
    int wn = (warp & 1) * 64;
    int lr = lane & 7, lsel = (lane >> 3) & 1, ltile = lane >> 4;
    int g = lane >> 2, tg = lane & 3;
    uint32_t abase = (uint32_t)__cvta_generic_to_shared(As);
    uint32_t bbase = (uint32_t)__cvta_generic_to_shared(Bs);

    float c[2][8][4];
    #pragma unroll
    for (int a = 0; a < 2; a++)
        #pragma unroll
        for (int b = 0; b < 8; b++)
            #pragma unroll
            for (int e = 0; e < 4; e++) c[a][b][e] = 0.f;

    #pragma unroll
    for (int k0 = 0; k0 < 128; k0 += 16) {
        uint32_t a[2][4];
        #pragma unroll
        for (int mt = 0; mt < 2; mt++) {
            int arow = wm + mt * 16 + lsel * 8 + lr;
            int akoff = k0 + ltile * 8;
            ldsm4(a[mt], abase + (arow * PRS + akoff) * 2);
        }
        #pragma unroll
        for (int ntp = 0; ntp < 4; ntp++) {
            int brow = wn + ntp * 16 + ltile * 8 + lr;
            int bkoff = k0 + lsel * 8;
            uint32_t b[4];
            ldsm4(b, bbase + (brow * PRS + bkoff) * 2);
            #pragma unroll
            for (int mt = 0; mt < 2; mt++) {
                mma_f16(c[mt][2*ntp],   a[mt], b[0], b[1]);
                mma_f16(c[mt][2*ntp+1], a[mt], b[2], b[3]);
            }
        }
    }

    #pragma unroll
    for (int nt = 0; nt < 8; nt++) {
        int n = wn + nt * 8 + 2 * tg;
        float bo0 = __ldg(bo + n), bo1 = __ldg(bo + n + 1);
        #pragma unroll
        for (int mt = 0; mt < 2; mt++) {
            #pragma unroll
            for (int rr = 0; rr < 2; rr++) {
                int m = m0 + wm + mt * 16 + g + rr * 8;
                float* dst = out + (size_t)m * CIN + n;
                *(float2*)dst = make_float2(c[mt][nt][rr*2+0] + bo0,
                                            c[mt][nt][rr*2+1] + bo1);
            }
        }
    }
}

// ---------------- launch ----------------
extern "C" void kernel_launch(void* const* d_in, const int* in_sizes, int n_in,
                              void* d_out, int out_size) {
    const float* x     = (const float*)d_in[0];
    const float* mask  = (const float*)d_in[1];
    const float* gamma = (const float*)d_in[2];
    const float* beta  = (const float*)d_in[3];
    const float* wbias = (const float*)d_in[4];
    const float* wq    = (const float*)d_in[5];
    const float* wk    = (const float*)d_in[6];
    const float* wv    = (const float*)d_in[7];
    const float* wg    = (const float*)d_in[8];
    const float* bg    = (const float*)d_in[9];
    const float* wo    = (const float*)d_in[10];
    const float* bo    = (const float*)d_in[11];
    float* out = (float*)d_out;

    const int smem_gemm = 2 * 128 * PRS * 2;           // 69632 (also covers 128*132*4 C-stage)
    const int smem_attn = (2 * 384 * SKS + 384) * 4;   // 112128
    cudaFuncSetAttribute(proj_mma_kernel, cudaFuncAttributeMaxDynamicSharedMemorySize, smem_gemm);
    cudaFuncSetAttribute(out_mma_kernel,  cudaFuncAttributeMaxDynamicSharedMemorySize, smem_gemm);
    cudaFuncSetAttribute(attn_f16_kernel, cudaFuncAttributeMaxDynamicSharedMemorySize, smem_attn);

    pack_kernel<<<256, 256>>>(wq, wk, wv, wg, wo);
    ln_kernel<<<M_TOT / 8, 256>>>(x, gamma, beta, wbias);
    proj_mma_kernel<<<dim3(NH, M_TOT / 128), 256, smem_gemm>>>(bg);
    attn_f16_kernel<<<dim3(NN, NH), 256, smem_attn>>>(mask);
    out_mma_kernel<<<M_TOT / 128, 256, smem_gemm>>>(bo, out);
}

// round 15
// speedup vs baseline: 1.4690x; 1.0003x over previous
#include <cuda_runtime.h>
#include <cuda_fp16.h>
#include <stdint.h>
#include <math.h>

#define NN 384
#define CIN 128
#define DH 32
#define NH 4
#define M_TOT (NN*NN)   // 147456

#define SKS 36          // attn smem row stride (u32) for K/V interleaved hi/lo
#define PRS 136         // proj/out smem row stride in fp16 (272B, conflict-free ldsm)
#define LOG2E 1.4426950408889634f

// ---------------- scratch ----------------
__device__ __half g_xnh[(size_t)M_TOT*CIN];     // layernormed x, fp16
__device__ float g_triB[(size_t)NH*M_TOT];      // [h][p], pre-scaled by log2e
__device__ float g_G[(size_t)M_TOT*CIN];        // [i][h][j][d]
__device__ __half g_OGh[(size_t)M_TOT*CIN];     // gated attention out, fp16 [m][h*32+d]
__device__ __half g_Bw[(size_t)512*CIN];        // qkvg weights [n=512][k=128] fp16
__device__ __half g_Bwo[(size_t)CIN*CIN];       // wo [c][k] fp16
// fp16 hi/lo planes, all [i][h][j][d]
__device__ __half g_Qh[(size_t)M_TOT*CIN];
__device__ __half g_Ql[(size_t)M_TOT*CIN];
__device__ __half g_Kh[(size_t)M_TOT*CIN];
__device__ __half g_Kl[(size_t)M_TOT*CIN];
__device__ __half g_Vh[(size_t)M_TOT*CIN];
__device__ __half g_Vl[(size_t)M_TOT*CIN];

// fp16 hi/lo split of a float pair
__device__ __forceinline__ void split_h(float a, float b, uint32_t& hi, uint32_t& lo) {
    __half2 H = __floats2half2_rn(a, b);
    float2 hf = __half22float2(H);
    __half2 L = __floats2half2_rn(a - hf.x, b - hf.y);
    hi = *(uint32_t*)&H; lo = *(uint32_t*)&L;
}

__device__ __forceinline__ void mma_f16(float* c, const uint32_t* a, uint32_t b0, uint32_t b1) {
    asm volatile("mma.sync.aligned.m16n8k16.row.col.f32.f16.f16.f32 "
        "{%0,%1,%2,%3}, {%4,%5,%6,%7}, {%8,%9}, {%0,%1,%2,%3};"
        : "+f"(c[0]), "+f"(c[1]), "+f"(c[2]), "+f"(c[3])
        : "r"(a[0]), "r"(a[1]), "r"(a[2]), "r"(a[3]), "r"(b0), "r"(b1));
}

__device__ __forceinline__ void ldsm4(uint32_t* r, uint32_t addr) {
    asm volatile("ldmatrix.sync.aligned.m8n8.x4.shared.b16 {%0,%1,%2,%3}, [%4];"
        : "=r"(r[0]), "=r"(r[1]), "=r"(r[2]), "=r"(r[3]) : "r"(addr));
}
__device__ __forceinline__ void ldsm4t(uint32_t* r, uint32_t addr) {
    asm volatile("ldmatrix.sync.aligned.m8n8.x4.trans.shared.b16 {%0,%1,%2,%3}, [%4];"
        : "=r"(r[0]), "=r"(r[1]), "=r"(r[2]), "=r"(r[3]) : "r"(addr));
}

// ---------------- K0: pack weights (fp16, [n][k] natural layout) ----------------
__global__ void pack_kernel(const float* __restrict__ wq, const float* __restrict__ wk,
                            const float* __restrict__ wv, const float* __restrict__ wg,
                            const float* __restrict__ wo) {
    int idx = blockIdx.x * 256 + threadIdx.x;
    if (idx < 512 * CIN) {
        int n = idx >> 7, k = idx & 127;
        int h = n >> 7, t = n & 127, sub = t >> 5, d = t & 31;
        const float* w = (sub == 0) ? wq : (sub == 1) ? wk : (sub == 2) ? wv : wg;
        float val = w[(h * DH + d) * CIN + k];
        if (sub == 0) val *= 0.17677669529663687f * LOG2E;   // 1/sqrt(32) * log2e
        g_Bw[idx] = __float2half_rn(val);
    }
    if (idx < CIN * CIN) {
        g_Bwo[idx] = __float2half_rn(wo[idx]);       // wo already [c][k]
    }
}

// ---------------- K1: LayerNorm only ----------------
__global__ void __launch_bounds__(256) ln_kernel(const float* __restrict__ x,
                                                 const float* __restrict__ gamma,
                                                 const float* __restrict__ beta) {
    int wid = threadIdx.x >> 5, lane = threadIdx.x & 31;
    int p = blockIdx.x * 8 + wid;
    const float4 v = ((const float4*)(x + (size_t)p * CIN))[lane];
    float s  = v.x + v.y + v.z + v.w;
    float sq = v.x*v.x + v.y*v.y + v.z*v.z + v.w*v.w;
    #pragma unroll
    for (int o = 16; o; o >>= 1) {
        s  += __shfl_xor_sync(~0u, s,  o);
        sq += __shfl_xor_sync(~0u, sq, o);
    }
    float mu   = s * (1.f / 128.f);
    float var  = sq * (1.f / 128.f) - mu * mu;
    float rstd = rsqrtf(var + 1e-5f);
    float4 g4 = ((const float4*)gamma)[lane];
    float4 b4 = ((const float4*)beta)[lane];
    float4 xn;
    xn.x = (v.x - mu) * rstd * g4.x + b4.x;
    xn.y = (v.y - mu) * rstd * g4.y + b4.y;
    xn.z = (v.z - mu) * rstd * g4.z + b4.z;
    xn.w = (v.w - mu) * rstd * g4.w + b4.w;

    __half2 h0 = __floats2half2_rn(xn.x, xn.y);
    __half2 h1 = __floats2half2_rn(xn.z, xn.w);
    uint2 u; u.x = *(uint32_t*)&h0; u.y = *(uint32_t*)&h1;
    ((uint2*)(g_xnh + (size_t)p * CIN))[lane] = u;
}

// ---------------- K2: projection GEMM (fp16 mma) + bias dot + staged epilogue ----------------
__global__ void __launch_bounds__(256, 1) proj_mma_kernel(const float* __restrict__ bg,
                                                          const float* __restrict__ wbias) {
    extern __shared__ char smc[];
    __half* As = (__half*)smc;           // [128][PRS]
    __half* Bs = As + 128 * PRS;         // [128][PRS]
    int tid = threadIdx.x;
    int h   = blockIdx.x;
    int m0  = blockIdx.y * 128;

    const uint4* Ag = (const uint4*)(g_xnh + (size_t)m0 * CIN);
    const uint4* Bg = (const uint4*)(g_Bw + (size_t)h * 128 * CIN);
    #pragma unroll
    for (int r = 0; r < 8; r++) {
        int f = tid + r * 256;           // 2048 uint4
        int row = f >> 4, c8 = f & 15;
        *(uint4*)(As + row * PRS + c8 * 8) = Ag[f];
        *(uint4*)(Bs + row * PRS + c8 * 8) = Bg[f];
    }
    __syncthreads();

    int warp = tid >> 5, lane = tid & 31;
    int wm = (warp >> 1) * 32;
    int wn = (warp & 1) * 64;
    int lr = lane & 7, lsel = (lane >> 3) & 1, ltile = lane >> 4;
    uint32_t abase = (uint32_t)__cvta_generic_to_shared(As);
    uint32_t bbase = (uint32_t)__cvta_generic_to_shared(Bs);

    float c[2][8][4];
    #pragma unroll
    for (int a = 0; a < 2; a++)
        #pragma unroll
        for (int b = 0; b < 8; b++)
            #pragma unroll
            for (int e = 0; e < 4; e++) c[a][b][e] = 0.f;

    #pragma unroll
    for (int k0 = 0; k0 < 128; k0 += 16) {
        uint32_t a[2][4];
        #pragma unroll
        for (int mt = 0; mt < 2; mt++) {
            int arow = wm + mt * 16 + lsel * 8 + lr;
            int akoff = k0 + ltile * 8;
            ldsm4(a[mt], abase + (arow * PRS + akoff) * 2);
        }
        #pragma unroll
        for (int ntp = 0; ntp < 4; ntp++) {
            int brow = wn + ntp * 16 + ltile * 8 + lr;
            int bkoff = k0 + lsel * 8;
            uint32_t b[4];
            ldsm4(b, bbase + (brow * PRS + bkoff) * 2);
            #pragma unroll
            for (int mt = 0; mt < 2; mt++) {
                mma_f16(c[mt][2*ntp],   a[mt], b[0], b[1]);
                mma_f16(c[mt][2*ntp+1], a[mt], b[2], b[3]);
            }
        }
    }

    // ---- triangle bias dot (threads 0-127, from fp16 As tile; scaled by log2e) ----
    if (tid < 128) {
        const __half2* xr = (const __half2*)(As + tid * PRS);
        const float2* wb = (const float2*)(wbias + h * CIN);
        float acc0 = 0.f, acc1 = 0.f;
        #pragma unroll
        for (int k = 0; k < 64; k++) {
            float2 xv = __half22float2(xr[k]);
            float2 wv = __ldg(wb + k);
            acc0 = fmaf(xv.x, wv.x, acc0);
            acc1 = fmaf(xv.y, wv.y, acc1);
        }
        g_triB[(size_t)h * M_TOT + m0 + tid] = (acc0 + acc1) * LOG2E;
    }
    __syncthreads();

    int g = lane >> 2, tg = lane & 3;
    float* Cs = (float*)smc;     // [128][132]
    #pragma unroll
    for (int nt = 0; nt < 8; nt++) {
        int col = wn + nt * 8 + 2 * tg;
        #pragma unroll
        for (int mt = 0; mt < 2; mt++) {
            int r0 = wm + mt * 16 + g;
            *(float2*)(Cs + r0 * 132 + col)       = make_float2(c[mt][nt][0], c[mt][nt][1]);
            *(float2*)(Cs + (r0 + 8) * 132 + col) = make_float2(c[mt][nt][2], c[mt][nt][3]);
        }
    }
    __syncthreads();

    int m_l = tid & 127, role = tid >> 7;
    int m = m0 + m_l;
    int i = m / NN, j = m - i * NN;
    size_t hb = (size_t)(i * NH + h) * NN * DH + (size_t)j * DH;
    const float* row = Cs + m_l * 132;

    if (role == 0) {
        #pragma unroll
        for (int s = 0; s < 2; s++) {
            const float* src = row + s * 32;
            __half* dh = (s == 0 ? g_Qh : g_Kh) + hb;
            __half* dl = (s == 0 ? g_Ql : g_Kl) + hb;
            #pragma unroll
            for (int b = 0; b < 4; b++) {
                float4 x0 = *(const float4*)(src + b * 8);
                float4 x1 = *(const float4*)(src + b * 8 + 4);
                uint32_t h0, l0, h1, l1, h2, l2, h3, l3;
                split_h(x0.x, x0.y, h0, l0);
                split_h(x0.z, x0.w, h1, l1);
                split_h(x1.x, x1.y, h2, l2);
                split_h(x1.z, x1.w, h3, l3);
                *(uint4*)(dh + b * 8) = make_uint4(h0, h1, h2, h3);
                *(uint4*)(dl + b * 8) = make_uint4(l0, l1, l2, l3);
            }
        }
    } else {
        {
            const float* src = row + 64;
            #pragma unroll
            for (int b = 0; b < 4; b++) {
                float4 x0 = *(const float4*)(src + b * 8);
                float4 x1 = *(const float4*)(src + b * 8 + 4);
                uint32_t h0, l0, h1, l1, h2, l2, h3, l3;
                split_h(x0.x, x0.y, h0, l0);
                split_h(x0.z, x0.w, h1, l1);
                split_h(x1.x, x1.y, h2, l2);
                split_h(x1.z, x1.w, h3, l3);
                *(uint4*)(g_Vh + hb + b * 8) = make_uint4(h0, h1, h2, h3);
                *(uint4*)(g_Vl + hb + b * 8) = make_uint4(l0, l1, l2, l3);
            }
        }
        {
            const float* src = row + 96;
            #pragma unroll
            for (int b = 0; b < 8; b++) {
                float4 x = *(const float4*)(src + b * 4);
                float4 o;
                o.x = 1.f / (1.f + __expf(-(x.x + __ldg(bg + h * DH + b * 4 + 0))));
                o.y = 1.f / (1.f + __expf(-(x.y + __ldg(bg + h * DH + b * 4 + 1))));
                o.z = 1.f / (1.f + __expf(-(x.z + __ldg(bg + h * DH + b * 4 + 2))));
                o.w = 1.f / (1.f + __expf(-(x.w + __ldg(bg + h * DH + b * 4 + 3))));
                *(float4*)(g_G + hb + b * 4) = o;
            }
        }
    }
}

// ---------------- K3: attention, fp16 mma, exp2-based softmax, bias L1-prefetch ----------------
__global__ void __launch_bounds__(256, 2) attn_f16_kernel(const float* __restrict__ mask) {
    extern __shared__ uint32_t smu[];
    uint32_t* Ks = smu;
    uint32_t* Vs = smu + 384 * SKS;
    float*    ms = (float*)(smu + 2 * 384 * SKS);

    int i = blockIdx.x, h = blockIdx.y;
    int tid = threadIdx.x, warp = tid >> 5, lane = tid & 31;
    int g = lane >> 2, tg = lane & 3;
    size_t base = (size_t)(i * NH + h) * NN * DH;
    uint32_t sbase = (uint32_t)__cvta_generic_to_shared(smu);
    uint32_t vbase = sbase + 384 * SKS * 4;

    {
        const uint4* Kh4 = (const uint4*)(g_Kh + base);
        const uint4* Kl4 = (const uint4*)(g_Kl + base);
        const uint4* Vh4 = (const uint4*)(g_Vh + base);
        const uint4* Vl4 = (const uint4*)(g_Vl + base);
        #pragma unroll
        for (int r = 0; r < 6; r++) {
            int f = tid + r * 256;
            int j = f >> 2, b = f & 3;
            *(uint4*)(Ks + j * SKS + 8 * b)     = Kh4[f];
            *(uint4*)(Ks + j * SKS + 8 * b + 4) = Kl4[f];
            *(uint4*)(Vs + j * SKS + 8 * b)     = Vh4[f];
            *(uint4*)(Vs + j * SKS + 8 * b + 4) = Vl4[f];
        }
        for (int t = tid; t < NN; t += 256)
            ms[t] = (__ldg(mask + (size_t)i * NN + t) - 1.f) * (1e9f * LOG2E);
    }
    __syncthreads();

    const float* biasH = g_triB + (size_t)h * M_TOT;
    const uint32_t* Qhp = (const uint32_t*)(g_Qh + base);
    const uint32_t* Qlp = (const uint32_t*)(g_Ql + base);

    int lr = lane & 7;
    int lsel = (lane >> 3) & 1;
    int ltile = lane >> 4;
    int pf_rowoff = (tg & 2) ? 8 : 0;
    int pf_coloff = (tg & 1) * 32;

    for (int qt = 0; qt < 3; qt++) {
        int q0 = qt * 128 + warp * 16;

        {
            const float* pf = biasH + (size_t)(q0 + g + pf_rowoff) * NN + pf_coloff;
            asm volatile("prefetch.global.L1 [%0];" :: "l"(pf));
        }

        uint32_t aQh[2][4], aQl[2][4];
        #pragma unroll
        for (int kc = 0; kc < 2; kc++) {
            int u0 = (q0 + g) * 16 + kc * 8 + tg;
            int u1 = (q0 + g + 8) * 16 + kc * 8 + tg;
            aQh[kc][0] = __ldg(Qhp + u0);     aQh[kc][1] = __ldg(Qhp + u1);
            aQh[kc][2] = __ldg(Qhp + u0 + 4); aQh[kc][3] = __ldg(Qhp + u1 + 4);
            aQl[kc][0] = __ldg(Qlp + u0);     aQl[kc][1] = __ldg(Qlp + u1);
            aQl[kc][2] = __ldg(Qlp + u0 + 4); aQl[kc][3] = __ldg(Qlp + u1 + 4);
        }

        float m0 = -1e30f, m1 = -1e30f, l0 = 0.f, l1 = 0.f;
        float O[4][4];
        #pragma unroll
        for (int a = 0; a < 4; a++)
            #pragma unroll
            for (int e = 0; e < 4; e++) O[a][e] = 0.f;

        for (int ch = 0; ch < 6; ch++) {
            int j0 = ch * 64;

            if (ch < 5) {
                const float* pf = biasH + (size_t)(q0 + g + pf_rowoff) * NN + (j0 + 64) + pf_coloff;
                asm volatile("prefetch.global.L1 [%0];" :: "l"(pf));
            }

            float c[8][4];
            #pragma unroll
            for (int nt = 0; nt < 8; nt++)
                #pragma unroll
                for (int e = 0; e < 4; e++) c[nt][e] = 0.f;

            #pragma unroll
            for (int kc = 0; kc < 2; kc++) {
                #pragma unroll
                for (int p = 0; p < 4; p++) {
                    int rowj = j0 + 16 * p + ltile * 8 + lr;
                    uint32_t addr = sbase + (rowj * SKS + 8 * (2 * kc + lsel)) * 4;
                    uint32_t bh[4], bl[4];
                    ldsm4(bh, addr);
                    ldsm4(bl, addr + 16);
                    mma_f16(c[2*p],   aQh[kc], bh[0], bh[1]);
                    mma_f16(c[2*p],   aQh[kc], bl[0], bl[1]);
                    mma_f16(c[2*p],   aQl[kc], bh[0], bh[1]);
                    mma_f16(c[2*p+1], aQh[kc], bh[2], bh[3]);
                    mma_f16(c[2*p+1], aQh[kc], bl[2], bl[3]);
                    mma_f16(c[2*p+1], aQl[kc], bh[2], bh[3]);
                }
            }

            float mx0 = -1e30f, mx1 = -1e30f;
            #pragma unroll
            for (int nt = 0; nt < 8; nt++) {
                int jj = j0 + nt * 8 + 2 * tg;
                float2 b0 = __ldg((const float2*)(biasH + (size_t)(q0 + g) * NN + jj));
                float2 b1 = __ldg((const float2*)(biasH + (size_t)(q0 + g + 8) * NN + jj));
                float2 mm = *(float2*)(ms + jj);
                c[nt][0] += b0.x + mm.x; c[nt][1] += b0.y + mm.y;
                c[nt][2] += b1.x + mm.x; c[nt][3] += b1.y + mm.y;
                mx0 = fmaxf(mx0, fmaxf(c[nt][0], c[nt][1]));
                mx1 = fmaxf(mx1, fmaxf(c[nt][2], c[nt][3]));
            }
            mx0 = fmaxf(mx0, __shfl_xor_sync(~0u, mx0, 1));
            mx0 = fmaxf(mx0, __shfl_xor_sync(~0u, mx0, 2));
            mx1 = fmaxf(mx1, __shfl_xor_sync(~0u, mx1, 1));
            mx1 = fmaxf(mx1, __shfl_xor_sync(~0u, mx1, 2));

            float mn0 = fmaxf(m0, mx0), mn1 = fmaxf(m1, mx1);
            float cr0 = exp2f(m0 - mn0), cr1 = exp2f(m1 - mn1);
            float s0 = 0.f, s1 = 0.f;
            #pragma unroll
            for (int nt = 0; nt < 8; nt++) {
                c[nt][0] = exp2f(c[nt][0] - mn0); c[nt][1] = exp2f(c[nt][1] - mn0);
                c[nt][2] = exp2f(c[nt][2] - mn1); c[nt][3] = exp2f(c[nt][3] - mn1);
                s0 += c[nt][0] + c[nt][1];
                s1 += c[nt][2] + c[nt][3];
            }
            s0 += __shfl_xor_sync(~0u, s0, 1); s0 += __shfl_xor_sync(~0u, s0, 2);
            s1 += __shfl_xor_sync(~0u, s1, 1); s1 += __shfl_xor_sync(~0u, s1, 2);
            l0 = l0 * cr0 + s0; l1 = l1 * cr1 + s1;
            m0 = mn0; m1 = mn1;
            #pragma unroll
            for (int nt2 = 0; nt2 < 4; nt2++) {
                O[nt2][0] *= cr0; O[nt2][1] *= cr0;
                O[nt2][2] *= cr1; O[nt2][3] *= cr1;
            }

            #pragma unroll
            for (int kc = 0; kc < 4; kc++) {
                uint32_t ph[4];
                __half2 p0 = __floats2half2_rn(c[2*kc][0],   c[2*kc][1]);
                __half2 p1 = __floats2half2_rn(c[2*kc][2],   c[2*kc][3]);
                __half2 p2 = __floats2half2_rn(c[2*kc+1][0], c[2*kc+1][1]);
                __half2 p3 = __floats2half2_rn(c[2*kc+1][2], c[2*kc+1][3]);
                ph[0] = *(uint32_t*)&p0; ph[1] = *(uint32_t*)&p1;
                ph[2] = *(uint32_t*)&p2; ph[3] = *(uint32_t*)&p3;
                int rowj = j0 + 16 * kc + lsel * 8 + lr;
                #pragma unroll
                for (int pd = 0; pd < 2; pd++) {
                    uint32_t addr = vbase + (rowj * SKS + 8 * (2 * pd + ltile)) * 4;
                    uint32_t bh[4], bl[4];
                    ldsm4t(bh, addr);
                    ldsm4t(bl, addr + 16);
                    mma_f16(O[2*pd],   ph, bh[0], bh[1]);
                    mma_f16(O[2*pd],   ph, bl[0], bl[1]);
                    mma_f16(O[2*pd+1], ph, bh[2], bh[3]);
                    mma_f16(O[2*pd+1], ph, bl[2], bl[3]);
                }
            }
        }

        float iv0 = 1.f / l0, iv1 = 1.f / l1;
        #pragma unroll
        for (int nt2 = 0; nt2 < 4; nt2++) {
            int d = nt2 * 8 + 2 * tg;
            int qa = q0 + g, qb = q0 + g + 8;
            float2 ga = *(const float2*)(g_G + base + (size_t)qa * DH + d);
            float2 gb = *(const float2*)(g_G + base + (size_t)qb * DH + d);
            __half2 oa = __floats2half2_rn(O[nt2][0] * iv0 * ga.x, O[nt2][1] * iv0 * ga.y);
            __half2 ob = __floats2half2_rn(O[nt2][2] * iv1 * gb.x, O[nt2][3] * iv1 * gb.y);
            *(uint32_t*)(g_OGh + (size_t)(i * NN + qa) * CIN + h * DH + d) = *(uint32_t*)&oa;
            *(uint32_t*)(g_OGh + (size_t)(i * NN + qb) * CIN + h * DH + d) = *(uint32_t*)&ob;
        }
    }
}

// ---------------- K4: output GEMM via fp16 mma ----------------
__global__ void __launch_bounds__(256, 1) out_mma_kernel(const float* __restrict__ bo,
                                                         float* __restrict__ out) {
    extern __shared__ char smc[];
    __half* As = (__half*)smc;           // [128][PRS]
    __half* Bs = As + 128 * PRS;
    int tid = threadIdx.x;
    int m0  = blockIdx.x * 128;

    const uint4* Ag = (const uint4*)(g_OGh + (size_t)m0 * CIN);
    const uint4* Bg = (const uint4*)g_Bwo;
    #pragma unroll
    for (int r = 0; r < 8; r++) {
        int f = tid + r * 256;
        int row = f >> 4, c8 = f & 15;
        *(uint4*)(As + row * PRS + c8 * 8) = Ag[f];
        *(uint4*)(Bs + row * PRS + c8 * 8) = Bg[f];
    }
    __syncthreads();

    int warp = tid >> 5, lane = tid & 31;
    int wm = (warp >> 1) * 32;
    int wn = (warp & 1) * 64;
    int lr = lane & 7, lsel = (lane >> 3) & 1, ltile = lane >> 4;
    int g = lane >> 2, tg = lane & 3;
    uint32_t abase = (uint32_t)__cvta_generic_to_shared(As);
    uint32_t bbase = (uint32_t)__cvta_generic_to_shared(Bs);

    float c[2][8][4];
    #pragma unroll
    for (int a = 0; a < 2; a++)
        #pragma unroll
        for (int b = 0; b < 8; b++)
            #pragma unroll
            for (int e = 0; e < 4; e++) c[a][b][e] = 0.f;

    #pragma unroll
    for (int k0 = 0; k0 < 128; k0 += 16) {
        uint32_t a[2][4];
        #pragma unroll
        for (int mt = 0; mt < 2; mt++) {
            int arow = wm + mt * 16 + lsel * 8 + lr;
            int akoff = k0 + ltile * 8;
            ldsm4(a[mt], abase + (arow * PRS + akoff) * 2);
        }
        #pragma unroll
        for (int ntp = 0; ntp < 4; ntp++) {
            int brow = wn + ntp * 16 + ltile * 8 + lr;
            int bkoff = k0 + lsel * 8;
            uint32_t b[4];
            ldsm4(b, bbase + (brow * PRS + bkoff) * 2);
            #pragma unroll
            for (int mt = 0; mt < 2; mt++) {
                mma_f16(c[mt][2*ntp],   a[mt], b[0], b[1]);
                mma_f16(c[mt][2*ntp+1], a[mt], b[2], b[3]);
            }
        }
    }

    #pragma unroll
    for (int nt = 0; nt < 8; nt++) {
        int n = wn + nt * 8 + 2 * tg;
        float bo0 = __ldg(bo + n), bo1 = __ldg(bo + n + 1);
        #pragma unroll
        for (int mt = 0; mt < 2; mt++) {
            #pragma unroll
            for (int rr = 0; rr < 2; rr++) {
                int m = m0 + wm + mt * 16 + g + rr * 8;
                float* dst = out + (size_t)m * CIN + n;
                *(float2*)dst = make_float2(c[mt][nt][rr*2+0] + bo0,
                                            c[mt][nt][rr*2+1] + bo1);
            }
        }
    }
}

// ---------------- launch ----------------
extern "C" void kernel_launch(void* const* d_in, const int* in_sizes, int n_in,
                              void* d_out, int out_size) {
    const float* x     = (const float*)d_in[0];
    const float* mask  = (const float*)d_in[1];
    const float* gamma = (const float*)d_in[2];
    const float* beta  = (const float*)d_in[3];
    const float* wbias = (const float*)d_in[4];
    const float* wq    = (const float*)d_in[5];
    const float* wk    = (const float*)d_in[6];
    const float* wv    = (const float*)d_in[7];
    const float* wg    = (const float*)d_in[8];
    const float* bg    = (const float*)d_in[9];
    const float* wo    = (const float*)d_in[10];
    const float* bo    = (const float*)d_in[11];
    float* out = (float*)d_out;

    const int smem_gemm = 2 * 128 * PRS * 2;           // 69632
    const int smem_attn = (2 * 384 * SKS + 384) * 4;   // 112128
    cudaFuncSetAttribute(proj_mma_kernel, cudaFuncAttributeMaxDynamicSharedMemorySize, smem_gemm);
    cudaFuncSetAttribute(out_mma_kernel,  cudaFuncAttributeMaxDynamicSharedMemorySize, smem_gemm);
    cudaFuncSetAttribute(attn_f16_kernel, cudaFuncAttributeMaxDynamicSharedMemorySize, smem_attn);

    pack_kernel<<<256, 256>>>(wq, wk, wv, wg, wo);
    ln_kernel<<<M_TOT / 8, 256>>>(x, gamma, beta);
    proj_mma_kernel<<<dim3(NH, M_TOT / 128), 256, smem_gemm>>>(bg, wbias);
    attn_f16_kernel<<<dim3(NN, NH), 256, smem_attn>>>(mask);
    out_mma_kernel<<<M_TOT / 128, 256, smem_gemm>>>(bo, out);
}